// round 14
// baseline (speedup 1.0000x reference)
#include <cuda_runtime.h>
#include <cuda_bf16.h>
#include <cstdint>

typedef __nv_bfloat16 bf16;
typedef uint32_t u32;

#define BATCH 2
#define SEQ   2048
#define DM    1024
#define NH    16
#define DH    64
#define MTOT  (BATCH * SEQ)   // 4096

#define SCALE2F 0.18033688011112042f   // 0.125 * log2(e)

// GEMM smem: 4 tiles (Ah,Al,Bh,Bl) x double buffer x [128][20] u32
#define TROW 20
#define TBUF (128 * TROW)
#define GEMM_SMEM (4 * 2 * TBUF * 4)

// attention smem (bf16 rows padded to 72); single K/V buffer
#define QLD  72
#define KVBUF (4 * 64 * QLD)
#define ATTN_SMEM ((2 * 128 * QLD + KVBUF) * 2)

// ---------------------------------------------------------------------------
// device scratch (allocation-free rule)
// ---------------------------------------------------------------------------
__device__ bf16 g_xh[MTOT * DM], g_xl[MTOT * DM];           // x hi/lo [m][k]
__device__ bf16 g_Wh[4 * DM * DM], g_Wl[4 * DM * DM];       // W^T hi/lo [w][n][k]
__device__ bf16 g_Qh[MTOT * DM], g_Ql[MTOT * DM];           // Q(scaled) [bh][s][d]
__device__ bf16 g_Kh[MTOT * DM], g_Kl[MTOT * DM];           // K [bh][s][d]
__device__ bf16 g_Vth[MTOT * DM], g_Vtl[MTOT * DM];         // V^T [bh][d][s]
__device__ bf16 g_Hh[MTOT * DM], g_Hl[MTOT * DM];           // attn out [m][k]

// ---------------------------------------------------------------------------
// helpers
// ---------------------------------------------------------------------------
__device__ __forceinline__ u32 smaddr(const void* p) {
    return (u32)__cvta_generic_to_shared(p);
}
__device__ __forceinline__ void cpa16(u32 s, const void* g) {
    asm volatile("cp.async.cg.shared.global [%0], [%1], 16;" :: "r"(s), "l"(g));
}
__device__ __forceinline__ void cpa_commit() { asm volatile("cp.async.commit_group;"); }
__device__ __forceinline__ void cpa_wait0()  { asm volatile("cp.async.wait_group 0;"); }

__device__ __forceinline__ void bsplit(float v, bf16& h, bf16& l) {
    h = __float2bfloat16(v);
    l = __float2bfloat16(v - __bfloat162float(h));
}
__device__ __forceinline__ u32 bpack(bf16 a, bf16 b) {
    __nv_bfloat162 t = __halves2bfloat162(a, b);
    return *reinterpret_cast<u32*>(&t);
}
__device__ __forceinline__ void mma2(float d[4], const u32 a[4], u32 b0, u32 b1) {
    asm volatile(
        "mma.sync.aligned.m16n8k16.row.col.f32.bf16.bf16.f32 "
        "{%0,%1,%2,%3}, {%4,%5,%6,%7}, {%8,%9}, {%0,%1,%2,%3};"
        : "+f"(d[0]), "+f"(d[1]), "+f"(d[2]), "+f"(d[3])
        : "r"(a[0]), "r"(a[1]), "r"(a[2]), "r"(a[3]), "r"(b0), "r"(b1));
}
__device__ __forceinline__ void ldm_x4(u32& r0, u32& r1, u32& r2, u32& r3, u32 a) {
    asm volatile("ldmatrix.sync.aligned.m8n8.x4.shared.b16 {%0,%1,%2,%3}, [%4];"
                 : "=r"(r0), "=r"(r1), "=r"(r2), "=r"(r3) : "r"(a));
}
__device__ __forceinline__ float ex2f(float x) {
    float r; asm("ex2.approx.ftz.f32 %0, %1;" : "=f"(r) : "f"(x)); return r;
}

// ---------------------------------------------------------------------------
// prologue: split x (vectorized); transpose + split W
// ---------------------------------------------------------------------------
__global__ __launch_bounds__(256)
void split_x_kernel(const float* __restrict__ x) {
    const int i = (blockIdx.x * 256 + threadIdx.x) << 2;
    float4 v = *(const float4*)(x + i);
    bf16 h0, l0, h1, l1, h2, l2, h3, l3;
    bsplit(v.x, h0, l0); bsplit(v.y, h1, l1);
    bsplit(v.z, h2, l2); bsplit(v.w, h3, l3);
    u32* ph = (u32*)(g_xh + i);
    u32* pl = (u32*)(g_xl + i);
    ph[0] = bpack(h0, h1); ph[1] = bpack(h2, h3);
    pl[0] = bpack(l0, l1); pl[1] = bpack(l2, l3);
}

__global__ __launch_bounds__(256)
void split_w_kernel(const float* __restrict__ Wq, const float* __restrict__ Wk,
                    const float* __restrict__ Wv, const float* __restrict__ Wo) {
    __shared__ float t[32][33];
    const int z = blockIdx.z;
    const float* W = (z == 0) ? Wq : (z == 1) ? Wk : (z == 2) ? Wv : Wo;
    bf16* oh = g_Wh + (size_t)z * DM * DM;
    bf16* ol = g_Wl + (size_t)z * DM * DM;
    const int k0 = blockIdx.x << 5, n0 = blockIdx.y << 5;
    const int tx = threadIdx.x & 31, ty = threadIdx.x >> 5;
    #pragma unroll
    for (int i = 0; i < 32; i += 8)
        t[ty + i][tx] = W[(size_t)(k0 + ty + i) * DM + n0 + tx];
    __syncthreads();
    #pragma unroll
    for (int i = 0; i < 32; i += 8) {
        bf16 h, l; bsplit(t[tx][ty + i], h, l);
        oh[(size_t)(n0 + ty + i) * DM + k0 + tx] = h;
        ol[(size_t)(n0 + ty + i) * DM + k0 + tx] = l;
    }
}

// ---------------------------------------------------------------------------
// bf16x3 GEMM core: ldmatrix frags, term-major MMA order (RAW spacing 4).
// CTA 128x128, BK=32 (2 x k16), 8 warps (2m x 4n), warp tile 64x32.
// ---------------------------------------------------------------------------
__device__ __forceinline__ void bgemm_core(const bf16* __restrict__ Ah,
                                           const bf16* __restrict__ Al,
                                           const bf16* __restrict__ Bh,
                                           const bf16* __restrict__ Bl,
                                           int m0, int n0,
                                           float acc[4][4][4], char* sm) {
    u32* AsH = (u32*)sm;
    u32* AsL = AsH + 2 * TBUF;
    u32* BsH = AsL + 2 * TBUF;
    u32* BsL = BsH + 2 * TBUF;

    const int tid  = threadIdx.x;
    const int lane = tid & 31, warp = tid >> 5;
    const int wm = warp & 1, wn = warp >> 1;
    const int lr = tid >> 1;
    const int lc = (tid & 1) << 3;

    const bf16* pAh = Ah + (size_t)(m0 + lr) * DM + (lc << 1);
    const bf16* pAl = Al + (size_t)(m0 + lr) * DM + (lc << 1);
    const bf16* pBh = Bh + (size_t)(n0 + lr) * DM + (lc << 1);
    const bf16* pBl = Bl + (size_t)(n0 + lr) * DM + (lc << 1);
    const u32 dst0 = lr * TROW + lc;

    const u32 aoff = ((u32)(wm * 64 + (lane & 7) + ((lane >> 3) & 1) * 8) * TROW
                      + (lane >> 4) * 4) * 4;
    const u32 boff = ((u32)(wn * 32 + (lane & 7) + ((lane & 16) >> 1)) * TROW
                      + ((lane >> 3) & 1) * 4) * 4;
    const u32 smB = smaddr(AsH);
    const u32 aAh = smB + aoff;
    const u32 aAl = aAh + 2 * TBUF * 4;
    const u32 aBh = smB + 4 * TBUF * 4 + boff;
    const u32 aBl = aBh + 2 * TBUF * 4;
    #define MTP (16 * TROW * 4)

#define LD_TILE(bufv, koff) do {                                          \
    u32 d_ = (bufv) * TBUF + dst0;                                        \
    cpa16(smaddr(AsH + d_),     pAh + (koff));                            \
    cpa16(smaddr(AsH + d_ + 4), pAh + (koff) + 8);                        \
    cpa16(smaddr(AsL + d_),     pAl + (koff));                            \
    cpa16(smaddr(AsL + d_ + 4), pAl + (koff) + 8);                        \
    cpa16(smaddr(BsH + d_),     pBh + (koff));                            \
    cpa16(smaddr(BsH + d_ + 4), pBh + (koff) + 8);                        \
    cpa16(smaddr(BsL + d_),     pBl + (koff));                            \
    cpa16(smaddr(BsL + d_ + 4), pBl + (koff) + 8);                        \
    cpa_commit(); } while (0)

    LD_TILE(0, 0);
    cpa_wait0();
    __syncthreads();

    int buf = 0;
    for (int kt = 32; kt <= DM; kt += 32) {
        const bool more = (kt < DM);
        if (more) LD_TILE(buf ^ 1, kt);

        const u32 bB = (u32)buf * TBUF * 4;
        #pragma unroll
        for (int ks = 0; ks < 2; ks++) {
            const u32 kb = ks * 32;
            u32 bhf[4][2], blf[4][2];
            ldm_x4(bhf[0][0], bhf[0][1], bhf[1][0], bhf[1][1], aBh + bB + kb);
            ldm_x4(bhf[2][0], bhf[2][1], bhf[3][0], bhf[3][1], aBh + bB + MTP + kb);
            ldm_x4(blf[0][0], blf[0][1], blf[1][0], blf[1][1], aBl + bB + kb);
            ldm_x4(blf[2][0], blf[2][1], blf[3][0], blf[3][1], aBl + bB + MTP + kb);
            #pragma unroll
            for (int mt = 0; mt < 4; mt++) {
                u32 ah[4], al[4];
                ldm_x4(ah[0], ah[1], ah[2], ah[3], aAh + bB + mt * MTP + kb);
                ldm_x4(al[0], al[1], al[2], al[3], aAl + bB + mt * MTP + kb);
                #pragma unroll
                for (int nt = 0; nt < 4; nt++)
                    mma2(acc[mt][nt], ah, bhf[nt][0], bhf[nt][1]);
                #pragma unroll
                for (int nt = 0; nt < 4; nt++)
                    mma2(acc[mt][nt], al, bhf[nt][0], bhf[nt][1]);
                #pragma unroll
                for (int nt = 0; nt < 4; nt++)
                    mma2(acc[mt][nt], ah, blf[nt][0], blf[nt][1]);
            }
        }
        if (more) {
            cpa_wait0();
            __syncthreads();
            buf ^= 1;
        }
    }
#undef LD_TILE
#undef MTP
}

// ---------------------------------------------------------------------------
// QKV projections -> split bf16 Q (scaled), K, V^T
// ---------------------------------------------------------------------------
__global__ __launch_bounds__(256, 2)
void qkv_gemm_kernel(const float* __restrict__ bq, const float* __restrict__ bk,
                     const float* __restrict__ bv) {
    extern __shared__ char sm[];
    const int m0 = blockIdx.y << 7;
    const int n0 = blockIdx.x << 7;
    const int which = blockIdx.z;
    const bf16* Bh = g_Wh + (size_t)which * DM * DM;
    const bf16* Bl = g_Wl + (size_t)which * DM * DM;
    const float* bias = (which == 0) ? bq : (which == 1) ? bk : bv;

    float acc[4][4][4] = {};
    bgemm_core(g_xh, g_xl, Bh, Bl, m0, n0, acc, sm);

    const int lane = threadIdx.x & 31;
    const int warp = threadIdx.x >> 5;
    const int wm = warp & 1, wn = warp >> 1;

    #pragma unroll
    for (int mt = 0; mt < 4; mt++) {
        #pragma unroll
        for (int nt = 0; nt < 4; nt++) {
            const int n = n0 + wn * 32 + nt * 8 + ((lane & 3) << 1);
            const int hd = n >> 6;
            const int d  = n & 63;
            const float bn0 = bias[n], bn1 = bias[n + 1];
            #pragma unroll
            for (int half = 0; half < 2; half++) {
                const int m = m0 + wm * 64 + mt * 16 + (lane >> 2) + half * 8;
                const int b = m >> 11;
                const int s = m & (SEQ - 1);
                const int bhq = (b << 4) + hd;
                float v0 = acc[mt][nt][half * 2 + 0] + bn0;
                float v1 = acc[mt][nt][half * 2 + 1] + bn1;
                if (which == 0) { v0 *= SCALE2F; v1 *= SCALE2F; }
                bf16 h0, l0, h1, l1;
                bsplit(v0, h0, l0);
                bsplit(v1, h1, l1);
                if (which < 2) {
                    bf16* dh_ = (which == 0) ? g_Qh : g_Kh;
                    bf16* dl_ = (which == 0) ? g_Ql : g_Kl;
                    const u32 idx = ((u32)(bhq * SEQ + s) << 5) + (d >> 1);
                    ((u32*)dh_)[idx] = bpack(h0, h1);
                    ((u32*)dl_)[idx] = bpack(l0, l1);
                } else {
                    const size_t base = ((size_t)(bhq * DH + d)) * SEQ + s;
                    g_Vth[base] = h0;        g_Vtl[base] = l0;
                    g_Vth[base + SEQ] = h1;  g_Vtl[base + SEQ] = l1;
                }
            }
        }
    }
}

// ---------------------------------------------------------------------------
// Output projection: out = H @ Wo + bo
// ---------------------------------------------------------------------------
__global__ __launch_bounds__(256, 2)
void out_gemm_kernel(const float* __restrict__ bo, float* __restrict__ out) {
    extern __shared__ char sm[];
    const int m0 = blockIdx.y << 7;
    const int n0 = blockIdx.x << 7;
    const bf16* Bh = g_Wh + (size_t)3 * DM * DM;
    const bf16* Bl = g_Wl + (size_t)3 * DM * DM;

    float acc[4][4][4] = {};
    bgemm_core(g_Hh, g_Hl, Bh, Bl, m0, n0, acc, sm);

    const int lane = threadIdx.x & 31;
    const int warp = threadIdx.x >> 5;
    const int wm = warp & 1, wn = warp >> 1;

    #pragma unroll
    for (int mt = 0; mt < 4; mt++) {
        #pragma unroll
        for (int nt = 0; nt < 4; nt++) {
            const int n = n0 + wn * 32 + nt * 8 + ((lane & 3) << 1);
            const float bn0 = bo[n], bn1 = bo[n + 1];
            #pragma unroll
            for (int half = 0; half < 2; half++) {
                const int m = m0 + wm * 64 + mt * 16 + (lane >> 2) + half * 8;
                float2 v = make_float2(acc[mt][nt][half * 2 + 0] + bn0,
                                       acc[mt][nt][half * 2 + 1] + bn1);
                *(float2*)&out[(size_t)m * DM + n] = v;
            }
        }
    }
}

// ---------------------------------------------------------------------------
// Tensor-core causal flash attention: single K/V buffer, ldmatrix frags,
// hoisted Q, MUFU exp2, 4-way spaced MMA accumulators.
// ---------------------------------------------------------------------------
__global__ __launch_bounds__(256, 2)
void attn_kernel() {
    extern __shared__ __align__(16) bf16 smb[];
    bf16* Qh = smb;                    // [128][QLD]
    bf16* Ql = Qh + 128 * QLD;
    bf16* KV = Ql + 128 * QLD;         // {Kh,Kl,Vh,Vl}[64][QLD]

    const int qt = gridDim.x - 1 - blockIdx.x;    // heavy tiles first
    const int bh = blockIdx.y;
    const int b  = bh >> 4;
    const int hd = bh & (NH - 1);
    const int qb = qt << 7;

    const int tid = threadIdx.x, lane = tid & 31, warp = tid >> 5;
    const int g = lane >> 2, q4 = lane & 3;

    // async-load Q tile (hi+lo)
    {
        const int r = tid >> 1, c0 = (tid & 1) << 5;
        const size_t go = ((size_t)bh * SEQ + qb + r) * DH + c0;
        u32 dh_ = smaddr(Qh + r * QLD + c0);
        u32 dl_ = smaddr(Ql + r * QLD + c0);
        cpa16(dh_,      g_Qh + go);      cpa16(dh_ + 16, g_Qh + go + 8);
        cpa16(dh_ + 32, g_Qh + go + 16); cpa16(dh_ + 48, g_Qh + go + 24);
        cpa16(dl_,      g_Ql + go);      cpa16(dl_ + 16, g_Ql + go + 8);
        cpa16(dl_ + 32, g_Ql + go + 16); cpa16(dl_ + 48, g_Ql + go + 24);
        cpa_commit();
    }
    cpa_wait0();
    __syncthreads();

    // hoist Q fragments (invariant over kt)
    u32 qah[4][4], qal[4][4];
    {
        const u32 qoff = ((u32)(warp * 16 + (lane & 15)) * QLD + ((lane >> 4) << 3)) * 2;
        const u32 aQ  = smaddr(Qh) + qoff;
        const u32 aQl = smaddr(Ql) + qoff;
        #pragma unroll
        for (int kk = 0; kk < 4; kk++) {
            ldm_x4(qah[kk][0], qah[kk][1], qah[kk][2], qah[kk][3], aQ  + kk * 32);
            ldm_x4(qal[kk][0], qal[kk][1], qal[kk][2], qal[kk][3], aQl + kk * 32);
        }
    }

    // K/V loader coords
    const int lrr = tid >> 2, lc0 = (tid & 3) << 4;
    const size_t gk0 = ((size_t)bh * SEQ + lrr) * DH + lc0;
    const size_t gv0 = ((size_t)bh * DH + lrr) * SEQ + lc0;
    const u32 kvdst = smaddr(KV) + (lrr * QLD + lc0) * 2;

    // B-fragment ldmatrix base
    const u32 boff = ((u32)(((lane & 7) | ((lane & 16) >> 1)) * QLD + (lane & 8))) * 2;
    const u32 aKh = smaddr(KV) + boff;
    const u32 aKl = aKh + 64 * QLD * 2;
    const u32 aVh = aKl + 64 * QLD * 2;
    const u32 aVl = aVh + 64 * QLD * 2;
    #define ROWP (16 * QLD * 2)

    float O[8][4] = {};
    float mrun0 = -1e30f, mrun1 = -1e30f, lrun0 = 0.f, lrun1 = 0.f;
    const int r0 = qb + warp * 16 + g;

    const int ktmax = 2 * qt + 1;
    for (int kt = 0; kt <= ktmax; kt++) {
        __syncthreads();
        {   // load K (hi/lo) and V^T (hi/lo) tile
            const size_t gk = gk0 + (size_t)(kt << 6) * DH;
            const size_t gv = gv0 + (kt << 6);
            u32 a = kvdst;
            cpa16(a, g_Kh + gk);  cpa16(a + 16, g_Kh + gk + 8);
            a += 64 * QLD * 2;
            cpa16(a, g_Kl + gk);  cpa16(a + 16, g_Kl + gk + 8);
            a += 64 * QLD * 2;
            cpa16(a, g_Vth + gv); cpa16(a + 16, g_Vth + gv + 8);
            a += 64 * QLD * 2;
            cpa16(a, g_Vtl + gv); cpa16(a + 16, g_Vtl + gv + 8);
            cpa_commit();
        }
        cpa_wait0();
        __syncthreads();

        // ---- S = Q K^T (bf16x3, 4-way accumulator spacing) ----
        float S[8][4];
        #pragma unroll
        for (int nt = 0; nt < 8; nt++) {
            S[nt][0] = 0.f; S[nt][1] = 0.f; S[nt][2] = 0.f; S[nt][3] = 0.f;
        }
        #pragma unroll
        for (int kk = 0; kk < 4; kk++) {
            #pragma unroll
            for (int pp = 0; pp < 2; pp++) {
                const int p0 = pp * 2, p1 = pp * 2 + 1;
                u32 b0, b1, b2, b3, c0, c1, c2, c3;
                u32 d0, d1, d2, d3, e0, e1, e2, e3;
                ldm_x4(b0, b1, b2, b3, aKh + p0 * ROWP + kk * 32);
                ldm_x4(c0, c1, c2, c3, aKh + p1 * ROWP + kk * 32);
                ldm_x4(d0, d1, d2, d3, aKl + p0 * ROWP + kk * 32);
                ldm_x4(e0, e1, e2, e3, aKl + p1 * ROWP + kk * 32);
                mma2(S[2 * p0],     qah[kk], b0, b1);
                mma2(S[2 * p0 + 1], qah[kk], b2, b3);
                mma2(S[2 * p1],     qah[kk], c0, c1);
                mma2(S[2 * p1 + 1], qah[kk], c2, c3);
                mma2(S[2 * p0],     qal[kk], b0, b1);
                mma2(S[2 * p0 + 1], qal[kk], b2, b3);
                mma2(S[2 * p1],     qal[kk], c0, c1);
                mma2(S[2 * p1 + 1], qal[kk], c2, c3);
                mma2(S[2 * p0],     qah[kk], d0, d1);
                mma2(S[2 * p0 + 1], qah[kk], d2, d3);
                mma2(S[2 * p1],     qah[kk], e0, e1);
                mma2(S[2 * p1 + 1], qah[kk], e2, e3);
            }
        }

        // ---- causal mask (diagonal-overlap tiles only) ----
        if (kt >= 2 * qt) {
            const int cb = (kt << 6) + (q4 << 1);
            #pragma unroll
            for (int nt = 0; nt < 8; nt++) {
                const int c = cb + nt * 8;
                if (c > r0)         S[nt][0] = -1e30f;
                if (c + 1 > r0)     S[nt][1] = -1e30f;
                if (c > r0 + 8)     S[nt][2] = -1e30f;
                if (c + 1 > r0 + 8) S[nt][3] = -1e30f;
            }
        }

        // ---- online softmax (base-2; MUFU exp2) ----
        float m0v = S[0][0], m1v = S[0][2];
        #pragma unroll
        for (int nt = 0; nt < 8; nt++) {
            m0v = fmaxf(m0v, fmaxf(S[nt][0], S[nt][1]));
            m1v = fmaxf(m1v, fmaxf(S[nt][2], S[nt][3]));
        }
        m0v = fmaxf(m0v, __shfl_xor_sync(0xffffffffu, m0v, 1));
        m0v = fmaxf(m0v, __shfl_xor_sync(0xffffffffu, m0v, 2));
        m1v = fmaxf(m1v, __shfl_xor_sync(0xffffffffu, m1v, 1));
        m1v = fmaxf(m1v, __shfl_xor_sync(0xffffffffu, m1v, 2));
        const float mn0 = fmaxf(mrun0, m0v), mn1 = fmaxf(mrun1, m1v);
        const float al0 = ex2f(mrun0 - mn0), al1 = ex2f(mrun1 - mn1);
        mrun0 = mn0; mrun1 = mn1;

        float l0 = 0.f, l1 = 0.f;
        #pragma unroll
        for (int nt = 0; nt < 8; nt++) {
            S[nt][0] = ex2f(S[nt][0] - mn0);
            S[nt][1] = ex2f(S[nt][1] - mn0);
            S[nt][2] = ex2f(S[nt][2] - mn1);
            S[nt][3] = ex2f(S[nt][3] - mn1);
            l0 += S[nt][0] + S[nt][1];
            l1 += S[nt][2] + S[nt][3];
        }
        l0 += __shfl_xor_sync(0xffffffffu, l0, 1);
        l0 += __shfl_xor_sync(0xffffffffu, l0, 2);
        l1 += __shfl_xor_sync(0xffffffffu, l1, 1);
        l1 += __shfl_xor_sync(0xffffffffu, l1, 2);
        lrun0 = lrun0 * al0 + l0;
        lrun1 = lrun1 * al1 + l1;
        #pragma unroll
        for (int dt = 0; dt < 8; dt++) {
            O[dt][0] *= al0; O[dt][1] *= al0;
            O[dt][2] *= al1; O[dt][3] *= al1;
        }

        // ---- O += P V (4-way accumulator spacing) ----
        #pragma unroll
        for (int kk = 0; kk < 4; kk++) {
            const int nt0 = kk * 2, nt1 = kk * 2 + 1;
            bf16 p0h, p0l, p1h, p1l, p2h, p2l, p3h, p3l;
            bf16 p4h, p4l, p5h, p5l, p6h, p6l, p7h, p7l;
            bsplit(S[nt0][0], p0h, p0l);  bsplit(S[nt0][1], p1h, p1l);
            bsplit(S[nt0][2], p2h, p2l);  bsplit(S[nt0][3], p3h, p3l);
            bsplit(S[nt1][0], p4h, p4l);  bsplit(S[nt1][1], p5h, p5l);
            bsplit(S[nt1][2], p6h, p6l);  bsplit(S[nt1][3], p7h, p7l);
            u32 pah[4] = {bpack(p0h, p1h), bpack(p2h, p3h),
                          bpack(p4h, p5h), bpack(p6h, p7h)};
            u32 pal[4] = {bpack(p0l, p1l), bpack(p2l, p3l),
                          bpack(p4l, p5l), bpack(p6l, p7l)};
            #pragma unroll
            for (int pp = 0; pp < 2; pp++) {
                const int p0 = pp * 2, p1 = pp * 2 + 1;
                u32 v0, v1, v2, v3, u0, u1, u2, u3;
                u32 w0, w1, w2, w3, z0, z1, z2, z3;
                ldm_x4(v0, v1, v2, v3, aVh + p0 * ROWP + kk * 32);
                ldm_x4(u0, u1, u2, u3, aVh + p1 * ROWP + kk * 32);
                ldm_x4(w0, w1, w2, w3, aVl + p0 * ROWP + kk * 32);
                ldm_x4(z0, z1, z2, z3, aVl + p1 * ROWP + kk * 32);
                mma2(O[2 * p0],     pah, v0, v1);
                mma2(O[2 * p0 + 1], pah, v2, v3);
                mma2(O[2 * p1],     pah, u0, u1);
                mma2(O[2 * p1 + 1], pah, u2, u3);
                mma2(O[2 * p0],     pal, v0, v1);
                mma2(O[2 * p0 + 1], pal, v2, v3);
                mma2(O[2 * p1],     pal, u0, u1);
                mma2(O[2 * p1 + 1], pal, u2, u3);
                mma2(O[2 * p0],     pah, w0, w1);
                mma2(O[2 * p0 + 1], pah, w2, w3);
                mma2(O[2 * p1],     pah, z0, z1);
                mma2(O[2 * p1 + 1], pah, z2, z3);
            }
        }
    }
    #undef ROWP

    // ---- epilogue: normalize, split, write g_Hh/g_Hl [B,S,DM] ----
    const float inv0 = 1.0f / lrun0, inv1 = 1.0f / lrun1;
    #pragma unroll
    for (int dt = 0; dt < 8; dt++) {
        const int d = hd * DH + dt * 8 + (q4 << 1);
        {
            bf16 h0, l0, h1, l1;
            bsplit(O[dt][0] * inv0, h0, l0);
            bsplit(O[dt][1] * inv0, h1, l1);
            const u32 idx = ((u32)(b * SEQ + r0) * DM + d) >> 1;
            ((u32*)g_Hh)[idx] = bpack(h0, h1);
            ((u32*)g_Hl)[idx] = bpack(l0, l1);
        }
        {
            bf16 h0, l0, h1, l1;
            bsplit(O[dt][2] * inv1, h0, l0);
            bsplit(O[dt][3] * inv1, h1, l1);
            const u32 idx = ((u32)(b * SEQ + r0 + 8) * DM + d) >> 1;
            ((u32*)g_Hh)[idx] = bpack(h0, h1);
            ((u32*)g_Hl)[idx] = bpack(l0, l1);
        }
    }
}

// ---------------------------------------------------------------------------
extern "C" void kernel_launch(void* const* d_in, const int* in_sizes, int n_in,
                              void* d_out, int out_size) {
    const float* x  = (const float*)d_in[0];
    const float* Wq = (const float*)d_in[1];
    const float* bq = (const float*)d_in[2];
    const float* Wk = (const float*)d_in[3];
    const float* bk = (const float*)d_in[4];
    const float* Wv = (const float*)d_in[5];
    const float* bv = (const float*)d_in[6];
    const float* Wo = (const float*)d_in[7];
    const float* bo = (const float*)d_in[8];
    float* out = (float*)d_out;

    // 0. splits
    split_x_kernel<<<MTOT * DM / 1024, 256>>>(x);
    split_w_kernel<<<dim3(DM / 32, DM / 32, 4), 256>>>(Wq, Wk, Wv, Wo);

    // 1. QKV projections
    cudaFuncSetAttribute(qkv_gemm_kernel,
                         cudaFuncAttributeMaxDynamicSharedMemorySize, GEMM_SMEM);
    qkv_gemm_kernel<<<dim3(DM / 128, MTOT / 128, 3), 256, GEMM_SMEM>>>(bq, bk, bv);

    // 2. tensor-core causal flash attention
    cudaFuncSetAttribute(attn_kernel,
                         cudaFuncAttributeMaxDynamicSharedMemorySize, ATTN_SMEM);
    attn_kernel<<<dim3(SEQ / 128, BATCH * NH), 256, ATTN_SMEM>>>();

    // 3. output projection
    cudaFuncSetAttribute(out_gemm_kernel,
                         cudaFuncAttributeMaxDynamicSharedMemorySize, GEMM_SMEM);
    out_gemm_kernel<<<dim3(DM / 128, MTOT / 128), 256, GEMM_SMEM>>>(bo, out);
}

// round 15
// speedup vs baseline: 1.4670x; 1.4670x over previous
#include <cuda_runtime.h>
#include <cuda_fp16.h>
#include <cstdint>

typedef __half f16;
typedef uint32_t u32;

#define BATCH 2
#define SEQ   2048
#define DM    1024
#define NH    16
#define DH    64
#define MTOT  (BATCH * SEQ)   // 4096

#define SCALE2F 0.18033688011112042f   // 0.125 * log2(e)

// GEMM smem: 3 tiles (Ah,Al,B) x double buffer x [128][20] u32
#define TROW 20
#define TBUF (128 * TROW)
#define GEMM_SMEM (3 * 2 * TBUF * 4)

// attention smem (fp16 rows padded to 72); single K/V buffer (K + Vt planes)
#define QLD  72
#define ATTN_SMEM ((2 * 128 * QLD + 2 * 64 * QLD) * 2)

// ---------------------------------------------------------------------------
// device scratch (allocation-free rule)
// ---------------------------------------------------------------------------
__device__ f16 g_xh[MTOT * DM], g_xl[MTOT * DM];       // x hi/lo [m][k]
__device__ f16 g_W[4 * DM * DM];                       // W^T fp16 [w][n][k]
__device__ f16 g_Qh[MTOT * DM], g_Ql[MTOT * DM];       // Q(scaled) hi/lo [bh][s][d]
__device__ f16 g_K[MTOT * DM];                         // K fp16 [bh][s][d]
__device__ f16 g_Vt[MTOT * DM];                        // V^T fp16 [bh][d][s]
__device__ f16 g_Hh[MTOT * DM], g_Hl[MTOT * DM];       // attn out hi/lo [m][k]

// ---------------------------------------------------------------------------
// helpers
// ---------------------------------------------------------------------------
__device__ __forceinline__ u32 smaddr(const void* p) {
    return (u32)__cvta_generic_to_shared(p);
}
__device__ __forceinline__ void cpa16(u32 s, const void* g) {
    asm volatile("cp.async.cg.shared.global [%0], [%1], 16;" :: "r"(s), "l"(g));
}
__device__ __forceinline__ void cpa_commit() { asm volatile("cp.async.commit_group;"); }
__device__ __forceinline__ void cpa_wait0()  { asm volatile("cp.async.wait_group 0;"); }

__device__ __forceinline__ void hsplit(float v, f16& h, f16& l) {
    h = __float2half_rn(v);
    l = __float2half_rn(v - __half2float(h));
}
__device__ __forceinline__ u32 hpack(f16 a, f16 b) {
    half2 t = __halves2half2(a, b);
    return *reinterpret_cast<u32*>(&t);
}
__device__ __forceinline__ void mma2(float d[4], const u32 a[4], u32 b0, u32 b1) {
    asm volatile(
        "mma.sync.aligned.m16n8k16.row.col.f32.f16.f16.f32 "
        "{%0,%1,%2,%3}, {%4,%5,%6,%7}, {%8,%9}, {%0,%1,%2,%3};"
        : "+f"(d[0]), "+f"(d[1]), "+f"(d[2]), "+f"(d[3])
        : "r"(a[0]), "r"(a[1]), "r"(a[2]), "r"(a[3]), "r"(b0), "r"(b1));
}
__device__ __forceinline__ void ldm_x4(u32& r0, u32& r1, u32& r2, u32& r3, u32 a) {
    asm volatile("ldmatrix.sync.aligned.m8n8.x4.shared.b16 {%0,%1,%2,%3}, [%4];"
                 : "=r"(r0), "=r"(r1), "=r"(r2), "=r"(r3) : "r"(a));
}
__device__ __forceinline__ float ex2f(float x) {
    float r; asm("ex2.approx.ftz.f32 %0, %1;" : "=f"(r) : "f"(x)); return r;
}

// ---------------------------------------------------------------------------
// prologue: split x (vectorized); transpose W to fp16
// ---------------------------------------------------------------------------
__global__ __launch_bounds__(256)
void split_x_kernel(const float* __restrict__ x) {
    const int i = (blockIdx.x * 256 + threadIdx.x) << 2;
    float4 v = *(const float4*)(x + i);
    f16 h0, l0, h1, l1, h2, l2, h3, l3;
    hsplit(v.x, h0, l0); hsplit(v.y, h1, l1);
    hsplit(v.z, h2, l2); hsplit(v.w, h3, l3);
    u32* ph = (u32*)(g_xh + i);
    u32* pl = (u32*)(g_xl + i);
    ph[0] = hpack(h0, h1); ph[1] = hpack(h2, h3);
    pl[0] = hpack(l0, l1); pl[1] = hpack(l2, l3);
}

__global__ __launch_bounds__(256)
void split_w_kernel(const float* __restrict__ Wq, const float* __restrict__ Wk,
                    const float* __restrict__ Wv, const float* __restrict__ Wo) {
    __shared__ float t[32][33];
    const int z = blockIdx.z;
    const float* W = (z == 0) ? Wq : (z == 1) ? Wk : (z == 2) ? Wv : Wo;
    f16* oh = g_W + (size_t)z * DM * DM;
    const int k0 = blockIdx.x << 5, n0 = blockIdx.y << 5;
    const int tx = threadIdx.x & 31, ty = threadIdx.x >> 5;
    #pragma unroll
    for (int i = 0; i < 32; i += 8)
        t[ty + i][tx] = W[(size_t)(k0 + ty + i) * DM + n0 + tx];
    __syncthreads();
    #pragma unroll
    for (int i = 0; i < 32; i += 8)
        oh[(size_t)(n0 + ty + i) * DM + k0 + tx] = __float2half_rn(t[tx][ty + i]);
}

// ---------------------------------------------------------------------------
// fp16x2 GEMM core: A double-fp16 (hi/lo), B plain fp16, ldmatrix frags.
// CTA 128x128, BK=32 (2 x k16), 8 warps (2m x 4n), warp tile 64x32.
// ---------------------------------------------------------------------------
__device__ __forceinline__ void hgemm_core(const f16* __restrict__ Ah,
                                           const f16* __restrict__ Al,
                                           const f16* __restrict__ B,
                                           int m0, int n0,
                                           float acc[4][4][4], char* sm) {
    u32* AsH = (u32*)sm;
    u32* AsL = AsH + 2 * TBUF;
    u32* Bs  = AsL + 2 * TBUF;

    const int tid  = threadIdx.x;
    const int lane = tid & 31, warp = tid >> 5;
    const int wm = warp & 1, wn = warp >> 1;
    const int lr = tid >> 1;
    const int lc = (tid & 1) << 3;

    const f16* pAh = Ah + (size_t)(m0 + lr) * DM + (lc << 1);
    const f16* pAl = Al + (size_t)(m0 + lr) * DM + (lc << 1);
    const f16* pB  = B  + (size_t)(n0 + lr) * DM + (lc << 1);
    const u32 dst0 = lr * TROW + lc;

    const u32 aoff = ((u32)(wm * 64 + (lane & 7) + ((lane >> 3) & 1) * 8) * TROW
                      + (lane >> 4) * 4) * 4;
    const u32 boff = ((u32)(wn * 32 + (lane & 7) + ((lane & 16) >> 1)) * TROW
                      + ((lane >> 3) & 1) * 4) * 4;
    const u32 smB = smaddr(AsH);
    const u32 aAh = smB + aoff;
    const u32 aAl = aAh + 2 * TBUF * 4;
    const u32 aB  = smB + 4 * TBUF * 4 + boff;
    #define MTP (16 * TROW * 4)

#define LD_TILE(bufv, koff) do {                                          \
    u32 d_ = (bufv) * TBUF + dst0;                                        \
    cpa16(smaddr(AsH + d_),     pAh + (koff));                            \
    cpa16(smaddr(AsH + d_ + 4), pAh + (koff) + 8);                        \
    cpa16(smaddr(AsL + d_),     pAl + (koff));                            \
    cpa16(smaddr(AsL + d_ + 4), pAl + (koff) + 8);                        \
    cpa16(smaddr(Bs + d_),      pB  + (koff));                            \
    cpa16(smaddr(Bs + d_ + 4),  pB  + (koff) + 8);                        \
    cpa_commit(); } while (0)

    LD_TILE(0, 0);
    cpa_wait0();
    __syncthreads();

    int buf = 0;
    for (int kt = 32; kt <= DM; kt += 32) {
        const bool more = (kt < DM);
        if (more) LD_TILE(buf ^ 1, kt);

        const u32 bB = (u32)buf * TBUF * 4;
        #pragma unroll
        for (int ks = 0; ks < 2; ks++) {
            const u32 kb = ks * 32;
            u32 bf[4][2];
            ldm_x4(bf[0][0], bf[0][1], bf[1][0], bf[1][1], aB + bB + kb);
            ldm_x4(bf[2][0], bf[2][1], bf[3][0], bf[3][1], aB + bB + MTP + kb);
            #pragma unroll
            for (int mt = 0; mt < 4; mt++) {
                u32 ah[4], al[4];
                ldm_x4(ah[0], ah[1], ah[2], ah[3], aAh + bB + mt * MTP + kb);
                ldm_x4(al[0], al[1], al[2], al[3], aAl + bB + mt * MTP + kb);
                #pragma unroll
                for (int nt = 0; nt < 4; nt++)
                    mma2(acc[mt][nt], ah, bf[nt][0], bf[nt][1]);
                #pragma unroll
                for (int nt = 0; nt < 4; nt++)
                    mma2(acc[mt][nt], al, bf[nt][0], bf[nt][1]);
            }
        }
        if (more) {
            cpa_wait0();
            __syncthreads();
            buf ^= 1;
        }
    }
#undef LD_TILE
#undef MTP
}

// ---------------------------------------------------------------------------
// QKV projections -> Q hi/lo (scaled), K fp16, V^T fp16
// ---------------------------------------------------------------------------
__global__ __launch_bounds__(256, 2)
void qkv_gemm_kernel(const float* __restrict__ bq, const float* __restrict__ bk,
                     const float* __restrict__ bv) {
    extern __shared__ char sm[];
    const int m0 = blockIdx.y << 7;
    const int n0 = blockIdx.x << 7;
    const int which = blockIdx.z;
    const f16* Bw = g_W + (size_t)which * DM * DM;
    const float* bias = (which == 0) ? bq : (which == 1) ? bk : bv;

    float acc[4][4][4] = {};
    hgemm_core(g_xh, g_xl, Bw, m0, n0, acc, sm);

    const int lane = threadIdx.x & 31;
    const int warp = threadIdx.x >> 5;
    const int wm = warp & 1, wn = warp >> 1;

    #pragma unroll
    for (int mt = 0; mt < 4; mt++) {
        #pragma unroll
        for (int nt = 0; nt < 4; nt++) {
            const int n = n0 + wn * 32 + nt * 8 + ((lane & 3) << 1);
            const int hd = n >> 6;
            const int d  = n & 63;
            const float bn0 = bias[n], bn1 = bias[n + 1];
            #pragma unroll
            for (int half = 0; half < 2; half++) {
                const int m = m0 + wm * 64 + mt * 16 + (lane >> 2) + half * 8;
                const int b = m >> 11;
                const int s = m & (SEQ - 1);
                const int bhq = (b << 4) + hd;
                float v0 = acc[mt][nt][half * 2 + 0] + bn0;
                float v1 = acc[mt][nt][half * 2 + 1] + bn1;
                if (which == 0) {
                    v0 *= SCALE2F; v1 *= SCALE2F;
                    f16 h0, l0, h1, l1;
                    hsplit(v0, h0, l0); hsplit(v1, h1, l1);
                    const u32 idx = ((u32)(bhq * SEQ + s) << 5) + (d >> 1);
                    ((u32*)g_Qh)[idx] = hpack(h0, h1);
                    ((u32*)g_Ql)[idx] = hpack(l0, l1);
                } else if (which == 1) {
                    const u32 idx = ((u32)(bhq * SEQ + s) << 5) + (d >> 1);
                    ((u32*)g_K)[idx] = hpack(__float2half_rn(v0), __float2half_rn(v1));
                } else {
                    const size_t base = ((size_t)(bhq * DH + d)) * SEQ + s;
                    g_Vt[base]       = __float2half_rn(v0);
                    g_Vt[base + SEQ] = __float2half_rn(v1);
                }
            }
        }
    }
}

// ---------------------------------------------------------------------------
// Output projection: out = H @ Wo + bo
// ---------------------------------------------------------------------------
__global__ __launch_bounds__(256, 2)
void out_gemm_kernel(const float* __restrict__ bo, float* __restrict__ out) {
    extern __shared__ char sm[];
    const int m0 = blockIdx.y << 7;
    const int n0 = blockIdx.x << 7;
    const f16* Bw = g_W + (size_t)3 * DM * DM;

    float acc[4][4][4] = {};
    hgemm_core(g_Hh, g_Hl, Bw, m0, n0, acc, sm);

    const int lane = threadIdx.x & 31;
    const int warp = threadIdx.x >> 5;
    const int wm = warp & 1, wn = warp >> 1;

    #pragma unroll
    for (int mt = 0; mt < 4; mt++) {
        #pragma unroll
        for (int nt = 0; nt < 4; nt++) {
            const int n = n0 + wn * 32 + nt * 8 + ((lane & 3) << 1);
            const float bn0 = bo[n], bn1 = bo[n + 1];
            #pragma unroll
            for (int half = 0; half < 2; half++) {
                const int m = m0 + wm * 64 + mt * 16 + (lane >> 2) + half * 8;
                float2 v = make_float2(acc[mt][nt][half * 2 + 0] + bn0,
                                       acc[mt][nt][half * 2 + 1] + bn1);
                *(float2*)&out[(size_t)m * DM + n] = v;
            }
        }
    }
}

// ---------------------------------------------------------------------------
// Tensor-core causal flash attention: fp16x2 (Q hi/lo, K/V plain fp16),
// ldmatrix frags, hoisted Q, MUFU exp2. CTA: 128 q-rows x 64-key tiles.
// ---------------------------------------------------------------------------
__global__ __launch_bounds__(256, 2)
void attn_kernel() {
    extern __shared__ __align__(16) f16 smb[];
    f16* Qh = smb;                     // [128][QLD]
    f16* Ql = Qh + 128 * QLD;
    f16* KV = Ql + 128 * QLD;          // {K, Vt}[64][QLD]

    const int qt = gridDim.x - 1 - blockIdx.x;    // heavy tiles first
    const int bh = blockIdx.y;
    const int b  = bh >> 4;
    const int hd = bh & (NH - 1);
    const int qb = qt << 7;

    const int tid = threadIdx.x, lane = tid & 31, warp = tid >> 5;
    const int g = lane >> 2, q4 = lane & 3;

    // async-load Q tile (hi+lo)
    {
        const int r = tid >> 1, c0 = (tid & 1) << 5;
        const size_t go = ((size_t)bh * SEQ + qb + r) * DH + c0;
        u32 dh_ = smaddr(Qh + r * QLD + c0);
        u32 dl_ = smaddr(Ql + r * QLD + c0);
        cpa16(dh_,      g_Qh + go);      cpa16(dh_ + 16, g_Qh + go + 8);
        cpa16(dh_ + 32, g_Qh + go + 16); cpa16(dh_ + 48, g_Qh + go + 24);
        cpa16(dl_,      g_Ql + go);      cpa16(dl_ + 16, g_Ql + go + 8);
        cpa16(dl_ + 32, g_Ql + go + 16); cpa16(dl_ + 48, g_Ql + go + 24);
        cpa_commit();
    }
    cpa_wait0();
    __syncthreads();

    // hoist Q fragments (invariant over kt)
    u32 qah[4][4], qal[4][4];
    {
        const u32 qoff = ((u32)(warp * 16 + (lane & 15)) * QLD + ((lane >> 4) << 3)) * 2;
        const u32 aQ  = smaddr(Qh) + qoff;
        const u32 aQl = smaddr(Ql) + qoff;
        #pragma unroll
        for (int kk = 0; kk < 4; kk++) {
            ldm_x4(qah[kk][0], qah[kk][1], qah[kk][2], qah[kk][3], aQ  + kk * 32);
            ldm_x4(qal[kk][0], qal[kk][1], qal[kk][2], qal[kk][3], aQl + kk * 32);
        }
    }

    // K/V loader coords
    const int lrr = tid >> 2, lc0 = (tid & 3) << 4;
    const size_t gk0 = ((size_t)bh * SEQ + lrr) * DH + lc0;
    const size_t gv0 = ((size_t)bh * DH + lrr) * SEQ + lc0;
    const u32 kvdst = smaddr(KV) + (lrr * QLD + lc0) * 2;

    // B-fragment ldmatrix base
    const u32 boff = ((u32)(((lane & 7) | ((lane & 16) >> 1)) * QLD + (lane & 8))) * 2;
    const u32 aK = smaddr(KV) + boff;
    const u32 aV = aK + 64 * QLD * 2;
    #define ROWP (16 * QLD * 2)

    float O[8][4] = {};
    float mrun0 = -1e30f, mrun1 = -1e30f, lrun0 = 0.f, lrun1 = 0.f;
    const int r0 = qb + warp * 16 + g;

    const int ktmax = 2 * qt + 1;
    for (int kt = 0; kt <= ktmax; kt++) {
        __syncthreads();
        {   // load K and V^T tile (fp16 planes)
            const size_t gk = gk0 + (size_t)(kt << 6) * DH;
            const size_t gv = gv0 + (kt << 6);
            u32 a = kvdst;
            cpa16(a, g_K + gk);   cpa16(a + 16, g_K + gk + 8);
            a += 64 * QLD * 2;
            cpa16(a, g_Vt + gv);  cpa16(a + 16, g_Vt + gv + 8);
            cpa_commit();
        }
        cpa_wait0();
        __syncthreads();

        // ---- S = Q K^T (fp16x2: qah + qal vs K) ----
        float S[8][4];
        #pragma unroll
        for (int nt = 0; nt < 8; nt++) {
            S[nt][0] = 0.f; S[nt][1] = 0.f; S[nt][2] = 0.f; S[nt][3] = 0.f;
        }
        #pragma unroll
        for (int kk = 0; kk < 4; kk++) {
            #pragma unroll
            for (int pp = 0; pp < 2; pp++) {
                const int p0 = pp * 2, p1 = pp * 2 + 1;
                u32 b0, b1, b2, b3, c0, c1, c2, c3;
                ldm_x4(b0, b1, b2, b3, aK + p0 * ROWP + kk * 32);
                ldm_x4(c0, c1, c2, c3, aK + p1 * ROWP + kk * 32);
                mma2(S[2 * p0],     qah[kk], b0, b1);
                mma2(S[2 * p0 + 1], qah[kk], b2, b3);
                mma2(S[2 * p1],     qah[kk], c0, c1);
                mma2(S[2 * p1 + 1], qah[kk], c2, c3);
                mma2(S[2 * p0],     qal[kk], b0, b1);
                mma2(S[2 * p0 + 1], qal[kk], b2, b3);
                mma2(S[2 * p1],     qal[kk], c0, c1);
                mma2(S[2 * p1 + 1], qal[kk], c2, c3);
            }
        }

        // ---- causal mask (diagonal-overlap tiles only) ----
        if (kt >= 2 * qt) {
            const int cb = (kt << 6) + (q4 << 1);
            #pragma unroll
            for (int nt = 0; nt < 8; nt++) {
                const int c = cb + nt * 8;
                if (c > r0)         S[nt][0] = -1e30f;
                if (c + 1 > r0)     S[nt][1] = -1e30f;
                if (c > r0 + 8)     S[nt][2] = -1e30f;
                if (c + 1 > r0 + 8) S[nt][3] = -1e30f;
            }
        }

        // ---- online softmax (base-2; MUFU exp2) ----
        float m0v = S[0][0], m1v = S[0][2];
        #pragma unroll
        for (int nt = 0; nt < 8; nt++) {
            m0v = fmaxf(m0v, fmaxf(S[nt][0], S[nt][1]));
            m1v = fmaxf(m1v, fmaxf(S[nt][2], S[nt][3]));
        }
        m0v = fmaxf(m0v, __shfl_xor_sync(0xffffffffu, m0v, 1));
        m0v = fmaxf(m0v, __shfl_xor_sync(0xffffffffu, m0v, 2));
        m1v = fmaxf(m1v, __shfl_xor_sync(0xffffffffu, m1v, 1));
        m1v = fmaxf(m1v, __shfl_xor_sync(0xffffffffu, m1v, 2));
        const float mn0 = fmaxf(mrun0, m0v), mn1 = fmaxf(mrun1, m1v);
        const float al0 = ex2f(mrun0 - mn0), al1 = ex2f(mrun1 - mn1);
        mrun0 = mn0; mrun1 = mn1;

        float l0 = 0.f, l1 = 0.f;
        #pragma unroll
        for (int nt = 0; nt < 8; nt++) {
            S[nt][0] = ex2f(S[nt][0] - mn0);
            S[nt][1] = ex2f(S[nt][1] - mn0);
            S[nt][2] = ex2f(S[nt][2] - mn1);
            S[nt][3] = ex2f(S[nt][3] - mn1);
            l0 += S[nt][0] + S[nt][1];
            l1 += S[nt][2] + S[nt][3];
        }
        l0 += __shfl_xor_sync(0xffffffffu, l0, 1);
        l0 += __shfl_xor_sync(0xffffffffu, l0, 2);
        l1 += __shfl_xor_sync(0xffffffffu, l1, 1);
        l1 += __shfl_xor_sync(0xffffffffu, l1, 2);
        lrun0 = lrun0 * al0 + l0;
        lrun1 = lrun1 * al1 + l1;
        #pragma unroll
        for (int dt = 0; dt < 8; dt++) {
            O[dt][0] *= al0; O[dt][1] *= al0;
            O[dt][2] *= al1; O[dt][3] *= al1;
        }

        // ---- O += P V (P hi/lo A-frags vs plain V) ----
        #pragma unroll
        for (int kk = 0; kk < 4; kk++) {
            const int nt0 = kk * 2, nt1 = kk * 2 + 1;
            f16 p0h, p0l, p1h, p1l, p2h, p2l, p3h, p3l;
            f16 p4h, p4l, p5h, p5l, p6h, p6l, p7h, p7l;
            hsplit(S[nt0][0], p0h, p0l);  hsplit(S[nt0][1], p1h, p1l);
            hsplit(S[nt0][2], p2h, p2l);  hsplit(S[nt0][3], p3h, p3l);
            hsplit(S[nt1][0], p4h, p4l);  hsplit(S[nt1][1], p5h, p5l);
            hsplit(S[nt1][2], p6h, p6l);  hsplit(S[nt1][3], p7h, p7l);
            u32 pah[4] = {hpack(p0h, p1h), hpack(p2h, p3h),
                          hpack(p4h, p5h), hpack(p6h, p7h)};
            u32 pal[4] = {hpack(p0l, p1l), hpack(p2l, p3l),
                          hpack(p4l, p5l), hpack(p6l, p7l)};
            #pragma unroll
            for (int pp = 0; pp < 2; pp++) {
                const int p0 = pp * 2, p1 = pp * 2 + 1;
                u32 v0, v1, v2, v3, u0, u1, u2, u3;
                ldm_x4(v0, v1, v2, v3, aV + p0 * ROWP + kk * 32);
                ldm_x4(u0, u1, u2, u3, aV + p1 * ROWP + kk * 32);
                mma2(O[2 * p0],     pah, v0, v1);
                mma2(O[2 * p0 + 1], pah, v2, v3);
                mma2(O[2 * p1],     pah, u0, u1);
                mma2(O[2 * p1 + 1], pah, u2, u3);
                mma2(O[2 * p0],     pal, v0, v1);
                mma2(O[2 * p0 + 1], pal, v2, v3);
                mma2(O[2 * p1],     pal, u0, u1);
                mma2(O[2 * p1 + 1], pal, u2, u3);
            }
        }
    }
    #undef ROWP

    // ---- epilogue: normalize, split, write g_Hh/g_Hl [B,S,DM] ----
    const float inv0 = 1.0f / lrun0, inv1 = 1.0f / lrun1;
    #pragma unroll
    for (int dt = 0; dt < 8; dt++) {
        const int d = hd * DH + dt * 8 + (q4 << 1);
        {
            f16 h0, l0, h1, l1;
            hsplit(O[dt][0] * inv0, h0, l0);
            hsplit(O[dt][1] * inv0, h1, l1);
            const u32 idx = ((u32)(b * SEQ + r0) * DM + d) >> 1;
            ((u32*)g_Hh)[idx] = hpack(h0, h1);
            ((u32*)g_Hl)[idx] = hpack(l0, l1);
        }
        {
            f16 h0, l0, h1, l1;
            hsplit(O[dt][2] * inv1, h0, l0);
            hsplit(O[dt][3] * inv1, h1, l1);
            const u32 idx = ((u32)(b * SEQ + r0 + 8) * DM + d) >> 1;
            ((u32*)g_Hh)[idx] = hpack(h0, h1);
            ((u32*)g_Hl)[idx] = hpack(l0, l1);
        }
    }
}

// ---------------------------------------------------------------------------
extern "C" void kernel_launch(void* const* d_in, const int* in_sizes, int n_in,
                              void* d_out, int out_size) {
    const float* x  = (const float*)d_in[0];
    const float* Wq = (const float*)d_in[1];
    const float* bq = (const float*)d_in[2];
    const float* Wk = (const float*)d_in[3];
    const float* bk = (const float*)d_in[4];
    const float* Wv = (const float*)d_in[5];
    const float* bv = (const float*)d_in[6];
    const float* Wo = (const float*)d_in[7];
    const float* bo = (const float*)d_in[8];
    float* out = (float*)d_out;

    // 0. splits
    split_x_kernel<<<MTOT * DM / 1024, 256>>>(x);
    split_w_kernel<<<dim3(DM / 32, DM / 32, 4), 256>>>(Wq, Wk, Wv, Wo);

    // 1. QKV projections (fp16x2)
    cudaFuncSetAttribute(qkv_gemm_kernel,
                         cudaFuncAttributeMaxDynamicSharedMemorySize, GEMM_SMEM);
    qkv_gemm_kernel<<<dim3(DM / 128, MTOT / 128, 3), 256, GEMM_SMEM>>>(bq, bk, bv);

    // 2. tensor-core causal flash attention (fp16x2)
    cudaFuncSetAttribute(attn_kernel,
                         cudaFuncAttributeMaxDynamicSharedMemorySize, ATTN_SMEM);
    attn_kernel<<<dim3(SEQ / 128, BATCH * NH), 256, ATTN_SMEM>>>();

    // 3. output projection (fp16x2)
    cudaFuncSetAttribute(out_gemm_kernel,
                         cudaFuncAttributeMaxDynamicSharedMemorySize, GEMM_SMEM);
    out_gemm_kernel<<<dim3(DM / 128, MTOT / 128), 256, GEMM_SMEM>>>(bo, out);
}

// round 16
// speedup vs baseline: 2.4515x; 1.6712x over previous
#include <cuda_runtime.h>
#include <cuda_fp16.h>
#include <cstdint>

typedef __half f16;
typedef uint32_t u32;

#define BATCH 2
#define SEQ   2048
#define DM    1024
#define NH    16
#define DH    64
#define MTOT  (BATCH * SEQ)   // 4096

#define SCALE2F 0.18033688011112042f   // 0.125 * log2(e)

// GEMM smem: 2 tiles (A,B) x double buffer x [128][20] u32
#define TROW 20
#define TBUF (128 * TROW)
#define GEMM_SMEM (2 * 2 * TBUF * 4)

// attention smem (fp16 rows padded to 72): Q + {K,Vt}
#define QLD  72
#define ATTN_SMEM ((128 * QLD + 2 * 64 * QLD) * 2)

// ---------------------------------------------------------------------------
// device scratch (allocation-free rule)
// ---------------------------------------------------------------------------
__device__ f16 g_x[MTOT * DM];          // x fp16 [m][k]
__device__ f16 g_W[4 * DM * DM];        // W^T fp16 [w][n][k]
__device__ f16 g_Q[MTOT * DM];          // Q(scaled) fp16 [bh][s][d]
__device__ f16 g_K[MTOT * DM];          // K fp16 [bh][s][d]
__device__ f16 g_Vt[MTOT * DM];         // V^T fp16 [bh][d][s]
__device__ f16 g_H[MTOT * DM];          // attn out fp16 [m][k]

// ---------------------------------------------------------------------------
// helpers
// ---------------------------------------------------------------------------
__device__ __forceinline__ u32 smaddr(const void* p) {
    return (u32)__cvta_generic_to_shared(p);
}
__device__ __forceinline__ void cpa16(u32 s, const void* g) {
    asm volatile("cp.async.cg.shared.global [%0], [%1], 16;" :: "r"(s), "l"(g));
}
__device__ __forceinline__ void cpa_commit() { asm volatile("cp.async.commit_group;"); }
__device__ __forceinline__ void cpa_wait0()  { asm volatile("cp.async.wait_group 0;"); }

__device__ __forceinline__ u32 hpack(f16 a, f16 b) {
    half2 t = __halves2half2(a, b);
    return *reinterpret_cast<u32*>(&t);
}
__device__ __forceinline__ void mma2(float d[4], const u32 a[4], u32 b0, u32 b1) {
    asm volatile(
        "mma.sync.aligned.m16n8k16.row.col.f32.f16.f16.f32 "
        "{%0,%1,%2,%3}, {%4,%5,%6,%7}, {%8,%9}, {%0,%1,%2,%3};"
        : "+f"(d[0]), "+f"(d[1]), "+f"(d[2]), "+f"(d[3])
        : "r"(a[0]), "r"(a[1]), "r"(a[2]), "r"(a[3]), "r"(b0), "r"(b1));
}
__device__ __forceinline__ void ldm_x4(u32& r0, u32& r1, u32& r2, u32& r3, u32 a) {
    asm volatile("ldmatrix.sync.aligned.m8n8.x4.shared.b16 {%0,%1,%2,%3}, [%4];"
                 : "=r"(r0), "=r"(r1), "=r"(r2), "=r"(r3) : "r"(a));
}
__device__ __forceinline__ float ex2f(float x) {
    float r; asm("ex2.approx.ftz.f32 %0, %1;" : "=f"(r) : "f"(x)); return r;
}

// ---------------------------------------------------------------------------
// prologue: convert x; transpose+convert W
// ---------------------------------------------------------------------------
__global__ __launch_bounds__(256)
void split_x_kernel(const float* __restrict__ x) {
    const int i = (blockIdx.x * 256 + threadIdx.x) << 2;
    float4 v = *(const float4*)(x + i);
    u32* p = (u32*)(g_x + i);
    p[0] = hpack(__float2half_rn(v.x), __float2half_rn(v.y));
    p[1] = hpack(__float2half_rn(v.z), __float2half_rn(v.w));
}

__global__ __launch_bounds__(256)
void split_w_kernel(const float* __restrict__ Wq, const float* __restrict__ Wk,
                    const float* __restrict__ Wv, const float* __restrict__ Wo) {
    __shared__ float t[32][33];
    const int z = blockIdx.z;
    const float* W = (z == 0) ? Wq : (z == 1) ? Wk : (z == 2) ? Wv : Wo;
    f16* oh = g_W + (size_t)z * DM * DM;
    const int k0 = blockIdx.x << 5, n0 = blockIdx.y << 5;
    const int tx = threadIdx.x & 31, ty = threadIdx.x >> 5;
    #pragma unroll
    for (int i = 0; i < 32; i += 8)
        t[ty + i][tx] = W[(size_t)(k0 + ty + i) * DM + n0 + tx];
    __syncthreads();
    #pragma unroll
    for (int i = 0; i < 32; i += 8)
        oh[(size_t)(n0 + ty + i) * DM + k0 + tx] = __float2half_rn(t[tx][ty + i]);
}

// ---------------------------------------------------------------------------
// fp16 GEMM core: ldmatrix frags. CTA 128x128, BK=32, 8 warps (2m x 4n).
// ---------------------------------------------------------------------------
__device__ __forceinline__ void hgemm_core(const f16* __restrict__ A,
                                           const f16* __restrict__ B,
                                           int m0, int n0,
                                           float acc[4][4][4], char* sm) {
    u32* As = (u32*)sm;
    u32* Bs = As + 2 * TBUF;

    const int tid  = threadIdx.x;
    const int lane = tid & 31, warp = tid >> 5;
    const int wm = warp & 1, wn = warp >> 1;
    const int lr = tid >> 1;
    const int lc = (tid & 1) << 3;

    const f16* pA = A + (size_t)(m0 + lr) * DM + (lc << 1);
    const f16* pB = B + (size_t)(n0 + lr) * DM + (lc << 1);
    const u32 dst0 = lr * TROW + lc;

    const u32 aoff = ((u32)(wm * 64 + (lane & 7) + ((lane >> 3) & 1) * 8) * TROW
                      + (lane >> 4) * 4) * 4;
    const u32 boff = ((u32)(wn * 32 + (lane & 7) + ((lane & 16) >> 1)) * TROW
                      + ((lane >> 3) & 1) * 4) * 4;
    const u32 smB = smaddr(As);
    const u32 aA = smB + aoff;
    const u32 aB = smB + 2 * TBUF * 4 + boff;
    #define MTP (16 * TROW * 4)

#define LD_TILE(bufv, koff) do {                                          \
    u32 d_ = (bufv) * TBUF + dst0;                                        \
    cpa16(smaddr(As + d_),     pA + (koff));                              \
    cpa16(smaddr(As + d_ + 4), pA + (koff) + 8);                          \
    cpa16(smaddr(Bs + d_),     pB + (koff));                              \
    cpa16(smaddr(Bs + d_ + 4), pB + (koff) + 8);                          \
    cpa_commit(); } while (0)

    LD_TILE(0, 0);
    cpa_wait0();
    __syncthreads();

    int buf = 0;
    for (int kt = 32; kt <= DM; kt += 32) {
        const bool more = (kt < DM);
        if (more) LD_TILE(buf ^ 1, kt);

        const u32 bB = (u32)buf * TBUF * 4;
        #pragma unroll
        for (int ks = 0; ks < 2; ks++) {
            const u32 kb = ks * 32;
            u32 bf[4][2];
            ldm_x4(bf[0][0], bf[0][1], bf[1][0], bf[1][1], aB + bB + kb);
            ldm_x4(bf[2][0], bf[2][1], bf[3][0], bf[3][1], aB + bB + MTP + kb);
            #pragma unroll
            for (int mt = 0; mt < 4; mt++) {
                u32 ah[4];
                ldm_x4(ah[0], ah[1], ah[2], ah[3], aA + bB + mt * MTP + kb);
                #pragma unroll
                for (int nt = 0; nt < 4; nt++)
                    mma2(acc[mt][nt], ah, bf[nt][0], bf[nt][1]);
            }
        }
        if (more) {
            cpa_wait0();
            __syncthreads();
            buf ^= 1;
        }
    }
#undef LD_TILE
#undef MTP
}

// ---------------------------------------------------------------------------
// QKV projections -> Q(scaled), K, V^T (all fp16)
// ---------------------------------------------------------------------------
__global__ __launch_bounds__(256, 2)
void qkv_gemm_kernel(const float* __restrict__ bq, const float* __restrict__ bk,
                     const float* __restrict__ bv) {
    extern __shared__ char sm[];
    const int m0 = blockIdx.y << 7;
    const int n0 = blockIdx.x << 7;
    const int which = blockIdx.z;
    const f16* Bw = g_W + (size_t)which * DM * DM;
    const float* bias = (which == 0) ? bq : (which == 1) ? bk : bv;

    float acc[4][4][4] = {};
    hgemm_core(g_x, Bw, m0, n0, acc, sm);

    const int lane = threadIdx.x & 31;
    const int warp = threadIdx.x >> 5;
    const int wm = warp & 1, wn = warp >> 1;

    #pragma unroll
    for (int mt = 0; mt < 4; mt++) {
        #pragma unroll
        for (int nt = 0; nt < 4; nt++) {
            const int n = n0 + wn * 32 + nt * 8 + ((lane & 3) << 1);
            const int hd = n >> 6;
            const int d  = n & 63;
            const float bn0 = bias[n], bn1 = bias[n + 1];
            #pragma unroll
            for (int half = 0; half < 2; half++) {
                const int m = m0 + wm * 64 + mt * 16 + (lane >> 2) + half * 8;
                const int b = m >> 11;
                const int s = m & (SEQ - 1);
                const int bhq = (b << 4) + hd;
                float v0 = acc[mt][nt][half * 2 + 0] + bn0;
                float v1 = acc[mt][nt][half * 2 + 1] + bn1;
                if (which == 0) {
                    v0 *= SCALE2F; v1 *= SCALE2F;
                    const u32 idx = ((u32)(bhq * SEQ + s) << 5) + (d >> 1);
                    ((u32*)g_Q)[idx] = hpack(__float2half_rn(v0), __float2half_rn(v1));
                } else if (which == 1) {
                    const u32 idx = ((u32)(bhq * SEQ + s) << 5) + (d >> 1);
                    ((u32*)g_K)[idx] = hpack(__float2half_rn(v0), __float2half_rn(v1));
                } else {
                    const size_t base = ((size_t)(bhq * DH + d)) * SEQ + s;
                    g_Vt[base]       = __float2half_rn(v0);
                    g_Vt[base + SEQ] = __float2half_rn(v1);
                }
            }
        }
    }
}

// ---------------------------------------------------------------------------
// Output projection: out = H @ Wo + bo
// ---------------------------------------------------------------------------
__global__ __launch_bounds__(256, 2)
void out_gemm_kernel(const float* __restrict__ bo, float* __restrict__ out) {
    extern __shared__ char sm[];
    const int m0 = blockIdx.y << 7;
    const int n0 = blockIdx.x << 7;
    const f16* Bw = g_W + (size_t)3 * DM * DM;

    float acc[4][4][4] = {};
    hgemm_core(g_H, Bw, m0, n0, acc, sm);

    const int lane = threadIdx.x & 31;
    const int warp = threadIdx.x >> 5;
    const int wm = warp & 1, wn = warp >> 1;

    #pragma unroll
    for (int mt = 0; mt < 4; mt++) {
        #pragma unroll
        for (int nt = 0; nt < 4; nt++) {
            const int n = n0 + wn * 32 + nt * 8 + ((lane & 3) << 1);
            const float bn0 = bo[n], bn1 = bo[n + 1];
            #pragma unroll
            for (int half = 0; half < 2; half++) {
                const int m = m0 + wm * 64 + mt * 16 + (lane >> 2) + half * 8;
                float2 v = make_float2(acc[mt][nt][half * 2 + 0] + bn0,
                                       acc[mt][nt][half * 2 + 1] + bn1);
                *(float2*)&out[(size_t)m * DM + n] = v;
            }
        }
    }
}

// ---------------------------------------------------------------------------
// Tensor-core causal flash attention: plain fp16 operands, ldmatrix frags,
// hoisted Q, MUFU exp2. CTA: 128 q-rows x 64-key tiles, 8 warps.
// ---------------------------------------------------------------------------
__global__ __launch_bounds__(256, 2)
void attn_kernel() {
    extern __shared__ __align__(16) f16 smb[];
    f16* Qs = smb;                     // [128][QLD]
    f16* KV = Qs + 128 * QLD;          // {K, Vt}[64][QLD]

    const int qt = gridDim.x - 1 - blockIdx.x;    // heavy tiles first
    const int bh = blockIdx.y;
    const int b  = bh >> 4;
    const int hd = bh & (NH - 1);
    const int qb = qt << 7;

    const int tid = threadIdx.x, lane = tid & 31, warp = tid >> 5;
    const int g = lane >> 2, q4 = lane & 3;

    // async-load Q tile
    {
        const int r = tid >> 1, c0 = (tid & 1) << 5;
        const size_t go = ((size_t)bh * SEQ + qb + r) * DH + c0;
        u32 dq = smaddr(Qs + r * QLD + c0);
        cpa16(dq,      g_Q + go);      cpa16(dq + 16, g_Q + go + 8);
        cpa16(dq + 32, g_Q + go + 16); cpa16(dq + 48, g_Q + go + 24);
        cpa_commit();
    }
    cpa_wait0();
    __syncthreads();

    // hoist Q fragments (invariant over kt)
    u32 qa[4][4];
    {
        const u32 qoff = ((u32)(warp * 16 + (lane & 15)) * QLD + ((lane >> 4) << 3)) * 2;
        const u32 aQ = smaddr(Qs) + qoff;
        #pragma unroll
        for (int kk = 0; kk < 4; kk++)
            ldm_x4(qa[kk][0], qa[kk][1], qa[kk][2], qa[kk][3], aQ + kk * 32);
    }

    // K/V loader coords
    const int lrr = tid >> 2, lc0 = (tid & 3) << 4;
    const size_t gk0 = ((size_t)bh * SEQ + lrr) * DH + lc0;
    const size_t gv0 = ((size_t)bh * DH + lrr) * SEQ + lc0;
    const u32 kvdst = smaddr(KV) + (lrr * QLD + lc0) * 2;

    // B-fragment ldmatrix base
    const u32 boff = ((u32)(((lane & 7) | ((lane & 16) >> 1)) * QLD + (lane & 8))) * 2;
    const u32 aK = smaddr(KV) + boff;
    const u32 aV = aK + 64 * QLD * 2;
    #define ROWP (16 * QLD * 2)

    float O[8][4] = {};
    float mrun0 = -1e30f, mrun1 = -1e30f, lrun0 = 0.f, lrun1 = 0.f;
    const int r0 = qb + warp * 16 + g;

    const int ktmax = 2 * qt + 1;
    for (int kt = 0; kt <= ktmax; kt++) {
        __syncthreads();
        {   // load K and V^T tile
            const size_t gk = gk0 + (size_t)(kt << 6) * DH;
            const size_t gv = gv0 + (kt << 6);
            u32 a = kvdst;
            cpa16(a, g_K + gk);   cpa16(a + 16, g_K + gk + 8);
            a += 64 * QLD * 2;
            cpa16(a, g_Vt + gv);  cpa16(a + 16, g_Vt + gv + 8);
            cpa_commit();
        }
        cpa_wait0();
        __syncthreads();

        // ---- S = Q K^T ----
        float S[8][4];
        #pragma unroll
        for (int nt = 0; nt < 8; nt++) {
            S[nt][0] = 0.f; S[nt][1] = 0.f; S[nt][2] = 0.f; S[nt][3] = 0.f;
        }
        #pragma unroll
        for (int kk = 0; kk < 4; kk++) {
            #pragma unroll
            for (int pp = 0; pp < 2; pp++) {
                const int p0 = pp * 2, p1 = pp * 2 + 1;
                u32 b0, b1, b2, b3, c0, c1, c2, c3;
                ldm_x4(b0, b1, b2, b3, aK + p0 * ROWP + kk * 32);
                ldm_x4(c0, c1, c2, c3, aK + p1 * ROWP + kk * 32);
                mma2(S[2 * p0],     qa[kk], b0, b1);
                mma2(S[2 * p0 + 1], qa[kk], b2, b3);
                mma2(S[2 * p1],     qa[kk], c0, c1);
                mma2(S[2 * p1 + 1], qa[kk], c2, c3);
            }
        }

        // ---- causal mask (diagonal-overlap tiles only) ----
        if (kt >= 2 * qt) {
            const int cb = (kt << 6) + (q4 << 1);
            #pragma unroll
            for (int nt = 0; nt < 8; nt++) {
                const int c = cb + nt * 8;
                if (c > r0)         S[nt][0] = -1e30f;
                if (c + 1 > r0)     S[nt][1] = -1e30f;
                if (c > r0 + 8)     S[nt][2] = -1e30f;
                if (c + 1 > r0 + 8) S[nt][3] = -1e30f;
            }
        }

        // ---- online softmax (base-2; MUFU exp2) ----
        float m0v = S[0][0], m1v = S[0][2];
        #pragma unroll
        for (int nt = 0; nt < 8; nt++) {
            m0v = fmaxf(m0v, fmaxf(S[nt][0], S[nt][1]));
            m1v = fmaxf(m1v, fmaxf(S[nt][2], S[nt][3]));
        }
        m0v = fmaxf(m0v, __shfl_xor_sync(0xffffffffu, m0v, 1));
        m0v = fmaxf(m0v, __shfl_xor_sync(0xffffffffu, m0v, 2));
        m1v = fmaxf(m1v, __shfl_xor_sync(0xffffffffu, m1v, 1));
        m1v = fmaxf(m1v, __shfl_xor_sync(0xffffffffu, m1v, 2));
        const float mn0 = fmaxf(mrun0, m0v), mn1 = fmaxf(mrun1, m1v);
        const float al0 = ex2f(mrun0 - mn0), al1 = ex2f(mrun1 - mn1);
        mrun0 = mn0; mrun1 = mn1;

        float l0 = 0.f, l1 = 0.f;
        #pragma unroll
        for (int nt = 0; nt < 8; nt++) {
            S[nt][0] = ex2f(S[nt][0] - mn0);
            S[nt][1] = ex2f(S[nt][1] - mn0);
            S[nt][2] = ex2f(S[nt][2] - mn1);
            S[nt][3] = ex2f(S[nt][3] - mn1);
            l0 += S[nt][0] + S[nt][1];
            l1 += S[nt][2] + S[nt][3];
        }
        l0 += __shfl_xor_sync(0xffffffffu, l0, 1);
        l0 += __shfl_xor_sync(0xffffffffu, l0, 2);
        l1 += __shfl_xor_sync(0xffffffffu, l1, 1);
        l1 += __shfl_xor_sync(0xffffffffu, l1, 2);
        lrun0 = lrun0 * al0 + l0;
        lrun1 = lrun1 * al1 + l1;
        #pragma unroll
        for (int dt = 0; dt < 8; dt++) {
            O[dt][0] *= al0; O[dt][1] *= al0;
            O[dt][2] *= al1; O[dt][3] *= al1;
        }

        // ---- O += P V (P direct fp16 A-frags) ----
        #pragma unroll
        for (int kk = 0; kk < 4; kk++) {
            const int nt0 = kk * 2, nt1 = kk * 2 + 1;
            u32 pa[4] = {
                hpack(__float2half_rn(S[nt0][0]), __float2half_rn(S[nt0][1])),
                hpack(__float2half_rn(S[nt0][2]), __float2half_rn(S[nt0][3])),
                hpack(__float2half_rn(S[nt1][0]), __float2half_rn(S[nt1][1])),
                hpack(__float2half_rn(S[nt1][2]), __float2half_rn(S[nt1][3]))};
            #pragma unroll
            for (int pp = 0; pp < 2; pp++) {
                const int p0 = pp * 2, p1 = pp * 2 + 1;
                u32 v0, v1, v2, v3, u0, u1, u2, u3;
                ldm_x4(v0, v1, v2, v3, aV + p0 * ROWP + kk * 32);
                ldm_x4(u0, u1, u2, u3, aV + p1 * ROWP + kk * 32);
                mma2(O[2 * p0],     pa, v0, v1);
                mma2(O[2 * p0 + 1], pa, v2, v3);
                mma2(O[2 * p1],     pa, u0, u1);
                mma2(O[2 * p1 + 1], pa, u2, u3);
            }
        }
    }
    #undef ROWP

    // ---- epilogue: normalize, write g_H fp16 [B,S,DM] ----
    const float inv0 = 1.0f / lrun0, inv1 = 1.0f / lrun1;
    #pragma unroll
    for (int dt = 0; dt < 8; dt++) {
        const int d = hd * DH + dt * 8 + (q4 << 1);
        {
            const u32 idx = ((u32)(b * SEQ + r0) * DM + d) >> 1;
            ((u32*)g_H)[idx] = hpack(__float2half_rn(O[dt][0] * inv0),
                                     __float2half_rn(O[dt][1] * inv0));
        }
        {
            const u32 idx = ((u32)(b * SEQ + r0 + 8) * DM + d) >> 1;
            ((u32*)g_H)[idx] = hpack(__float2half_rn(O[dt][2] * inv1),
                                     __float2half_rn(O[dt][3] * inv1));
        }
    }
}

// ---------------------------------------------------------------------------
extern "C" void kernel_launch(void* const* d_in, const int* in_sizes, int n_in,
                              void* d_out, int out_size) {
    const float* x  = (const float*)d_in[0];
    const float* Wq = (const float*)d_in[1];
    const float* bq = (const float*)d_in[2];
    const float* Wk = (const float*)d_in[3];
    const float* bk = (const float*)d_in[4];
    const float* Wv = (const float*)d_in[5];
    const float* bv = (const float*)d_in[6];
    const float* Wo = (const float*)d_in[7];
    const float* bo = (const float*)d_in[8];
    float* out = (float*)d_out;

    // 0. fp16 conversions
    split_x_kernel<<<MTOT * DM / 1024, 256>>>(x);
    split_w_kernel<<<dim3(DM / 32, DM / 32, 4), 256>>>(Wq, Wk, Wv, Wo);

    // 1. QKV projections (fp16)
    cudaFuncSetAttribute(qkv_gemm_kernel,
                         cudaFuncAttributeMaxDynamicSharedMemorySize, GEMM_SMEM);
    qkv_gemm_kernel<<<dim3(DM / 128, MTOT / 128, 3), 256, GEMM_SMEM>>>(bq, bk, bv);

    // 2. tensor-core causal flash attention (fp16)
    cudaFuncSetAttribute(attn_kernel,
                         cudaFuncAttributeMaxDynamicSharedMemorySize, ATTN_SMEM);
    attn_kernel<<<dim3(SEQ / 128, BATCH * NH), 256, ATTN_SMEM>>>();

    // 3. output projection (fp16)
    cudaFuncSetAttribute(out_gemm_kernel,
                         cudaFuncAttributeMaxDynamicSharedMemorySize, GEMM_SMEM);
    out_gemm_kernel<<<dim3(DM / 128, MTOT / 128), 256, GEMM_SMEM>>>(bo, out);
}